// round 8
// baseline (speedup 1.0000x reference)
#include <cuda_runtime.h>

// Net_32521492365587 — tiny LSTM ensemble + dense decode, single scalar output.
//
// out = (W1^T·W2)·feat + (W2·b1 + b2)   [no nonlinearity between W1 and W2]
// v = W1^T·W2 and c computed concurrently with the gate phase; ONE barrier.
//
// R8: the block was LSU-issue-bound (~970 warp LDG instrs). v phase reworked:
// each v thread owns a COLUMN PAIR (float2 W1 loads) and W2 is read with
// vector loads -> v-phase LDG instrs drop ~760 -> ~290. 13 warps total.
//
// Thread plan (416 threads, 13 warps):
//   warps  0..3  (tid   0..127): gen gate lanes, active tid<100 -> s_feat[0..99]
//   warps  4..5  (tid 128..191): opp gate lanes, active o<50    -> s_feat[100..149]
//   warps  6..8  (tid 192..287): v-half0 (m 0..37),  pair i2<75 -> s_v0[2i2..]
//   warps  9..11 (tid 288..383): v-half1 (m 38..74), pair i2<75 -> s_v1[2i2..]
//   warp  12     (tid 384..415): c = W2.b1+b2 (regs); post-bar dot -> out

__device__ __forceinline__ float sigmoid_f(float v) {
    return 1.0f / (1.0f + __expf(-v));
}

__device__ __forceinline__ float tanh_f(float v) {
    // tanh(v) = 1 - 2/(e^(2v)+1); EX2 + RCP, branch-free, rel err ~1e-6
    const float e = __expf(2.0f * v);
    return fmaf(-2.0f, __frcp_rn(e + 1.0f), 1.0f);
}

__device__ __forceinline__ float warp_sum(float v) {
    #pragma unroll
    for (int off = 16; off; off >>= 1)
        v += __shfl_xor_sync(0xffffffffu, v, off);
    return v;
}

__global__ __launch_bounds__(416, 1)
void net_kernel(const float* __restrict__ x,
                const float* __restrict__ h0_gen,
                const float* __restrict__ c0_gen,
                const float* __restrict__ W_ih_opp,
                const float* __restrict__ b_ih_opp,
                const float* __restrict__ b_hh_opp,
                const float* __restrict__ W_ih_gen,
                const float* __restrict__ W_hh_gen,
                const float* __restrict__ b_ih_gen,
                const float* __restrict__ b_hh_gen,
                const float* __restrict__ W1,
                const float* __restrict__ b1,
                const float* __restrict__ W2,
                const float* __restrict__ b2,
                float* __restrict__ out)
{
    __shared__ float s_feat[152];
    __shared__ float s_v0[152];
    __shared__ float s_v1[152];

    const int tid  = threadIdx.x;
    const int warp = tid >> 5;
    const int lane = tid & 31;

    float c_reg = 0.0f;            // live only in warp 12

    if (warp < 4) {
        // ================= gen lanes (tid 0..99) =============================
        if (tid < 100) {
            const int g = tid / 10;
            const int j = tid - g * 10;

            const float4 xv0 = reinterpret_cast<const float4*>(x)[0];
            const float4 xv1 = reinterpret_cast<const float4*>(x)[1];
            float2 h2[5];
            const float2* __restrict__ h0p = reinterpret_cast<const float2*>(h0_gen + g * 10);
            #pragma unroll
            for (int k = 0; k < 5; ++k) h2[k] = h0p[k];
            const float c0v = c0_gen[tid];

            float gate[4];
            #pragma unroll
            for (int k = 0; k < 4; ++k) {
                const int row = g * 40 + k * 10 + j;
                const float4* __restrict__ wi = reinterpret_cast<const float4*>(W_ih_gen + row * 8);
                const float2* __restrict__ wh = reinterpret_cast<const float2*>(W_hh_gen + row * 10);
                float acc = b_ih_gen[row] + b_hh_gen[row];
                const float4 a = wi[0], b = wi[1];
                acc = fmaf(a.x, xv0.x, acc); acc = fmaf(a.y, xv0.y, acc);
                acc = fmaf(a.z, xv0.z, acc); acc = fmaf(a.w, xv0.w, acc);
                acc = fmaf(b.x, xv1.x, acc); acc = fmaf(b.y, xv1.y, acc);
                acc = fmaf(b.z, xv1.z, acc); acc = fmaf(b.w, xv1.w, acc);
                #pragma unroll
                for (int kk = 0; kk < 5; ++kk) {
                    const float2 w = wh[kk];
                    acc = fmaf(w.x, h2[kk].x, acc);
                    acc = fmaf(w.y, h2[kk].y, acc);
                }
                gate[k] = acc;
            }
            // gate order i,f,g,o
            const float c2 = sigmoid_f(gate[1]) * c0v + sigmoid_f(gate[0]) * tanh_f(gate[2]);
            s_feat[tid] = sigmoid_f(gate[3]) * tanh_f(c2);
        }
    } else if (warp < 6) {
        // ================= opp lanes (o = tid-128, active o<50) ==============
        // zero initial state -> f-gate dead, c2 = sig(i)*tanh(g)
        const int o = tid - 128;
        if (o < 50) {
            const float4 xv0 = reinterpret_cast<const float4*>(x)[0];
            const float4 xv1 = reinterpret_cast<const float4*>(x)[1];
            const int rows[3] = { o, 100 + o, 150 + o };   // i, g, o rows
            float gv[3];
            #pragma unroll
            for (int k = 0; k < 3; ++k) {
                const int row = rows[k];
                const float4* __restrict__ w = reinterpret_cast<const float4*>(W_ih_opp + row * 8);
                float acc = b_ih_opp[row] + b_hh_opp[row];
                const float4 a = w[0], b = w[1];
                acc = fmaf(a.x, xv0.x, acc); acc = fmaf(a.y, xv0.y, acc);
                acc = fmaf(a.z, xv0.z, acc); acc = fmaf(a.w, xv0.w, acc);
                acc = fmaf(b.x, xv1.x, acc); acc = fmaf(b.y, xv1.y, acc);
                acc = fmaf(b.z, xv1.z, acc); acc = fmaf(b.w, xv1.w, acc);
                gv[k] = acc;
            }
            const float c2 = sigmoid_f(gv[0]) * tanh_f(gv[1]);
            s_feat[100 + o] = sigmoid_f(gv[2]) * tanh_f(c2);
        }
    } else if (warp < 9) {
        // ---- v-half0: columns (2*i2, 2*i2+1), m = 0..37 ----
        const int i2 = tid - 192;
        if (i2 < 75) {
            // W2[0..37] via 9x float4 + 1x float2 (vector loads)
            float w2s[38];
            {
                const float4* __restrict__ w24 = reinterpret_cast<const float4*>(W2);
                #pragma unroll
                for (int t = 0; t < 9; ++t) {
                    const float4 v4 = w24[t];
                    w2s[4 * t + 0] = v4.x; w2s[4 * t + 1] = v4.y;
                    w2s[4 * t + 2] = v4.z; w2s[4 * t + 3] = v4.w;
                }
                const float2 v2 = reinterpret_cast<const float2*>(W2)[18];  // m=36,37
                w2s[36] = v2.x; w2s[37] = v2.y;
            }
            const float2* __restrict__ W1f2 = reinterpret_cast<const float2*>(W1);
            float2 a0 = make_float2(0.f, 0.f), a1 = make_float2(0.f, 0.f);
            #pragma unroll
            for (int m = 0; m < 38; m += 2) {
                const float2 p0 = W1f2[m * 75 + i2];
                const float2 p1 = W1f2[(m + 1) * 75 + i2];
                a0.x = fmaf(w2s[m], p0.x, a0.x);
                a0.y = fmaf(w2s[m], p0.y, a0.y);
                a1.x = fmaf(w2s[m + 1], p1.x, a1.x);
                a1.y = fmaf(w2s[m + 1], p1.y, a1.y);
            }
            reinterpret_cast<float2*>(s_v0)[i2] = make_float2(a0.x + a1.x, a0.y + a1.y);
        }
    } else if (warp < 12) {
        // ---- v-half1: columns (2*i2, 2*i2+1), m = 38..74 ----
        const int i2 = tid - 288;
        if (i2 < 75) {
            // W2[38..74] via 18x float2 + 1 scalar
            float w2s[37];
            {
                const float2* __restrict__ w22 = reinterpret_cast<const float2*>(W2);
                #pragma unroll
                for (int t = 0; t < 18; ++t) {
                    const float2 v2 = w22[19 + t];          // m = 38+2t, 39+2t
                    w2s[2 * t]     = v2.x;
                    w2s[2 * t + 1] = v2.y;
                }
                w2s[36] = W2[74];
            }
            const float2* __restrict__ W1f2 = reinterpret_cast<const float2*>(W1);
            float2 a0 = make_float2(0.f, 0.f), a1 = make_float2(0.f, 0.f);
            #pragma unroll
            for (int t = 0; t < 36; t += 2) {
                const float2 p0 = W1f2[(38 + t) * 75 + i2];
                const float2 p1 = W1f2[(39 + t) * 75 + i2];
                a0.x = fmaf(w2s[t], p0.x, a0.x);
                a0.y = fmaf(w2s[t], p0.y, a0.y);
                a1.x = fmaf(w2s[t + 1], p1.x, a1.x);
                a1.y = fmaf(w2s[t + 1], p1.y, a1.y);
            }
            {   // m = 74
                const float2 p = W1f2[74 * 75 + i2];
                a0.x = fmaf(w2s[36], p.x, a0.x);
                a0.y = fmaf(w2s[36], p.y, a0.y);
            }
            reinterpret_cast<float2*>(s_v1)[i2] = make_float2(a0.x + a1.x, a0.y + a1.y);
        }
    } else {
        // ---- warp 12: c = W2.b1 + b2, kept in registers ----
        float acc = 0.0f;
        #pragma unroll
        for (int m = lane; m < 75; m += 32)
            acc = fmaf(W2[m], b1[m], acc);
        c_reg = warp_sum(acc) + __ldg(b2);
    }
    __syncthreads();

    // ---- tail: out = sum_i (v0[i]+v1[i])*feat[i] + c   (warp 12) ----
    if (warp == 12) {
        float acc = 0.0f;
        #pragma unroll
        for (int i = lane; i < 150; i += 32)
            acc = fmaf(s_v0[i] + s_v1[i], s_feat[i], acc);
        acc = warp_sum(acc);
        if (lane == 0) out[0] = acc + c_reg;
    }
}

extern "C" void kernel_launch(void* const* d_in, const int* in_sizes, int n_in,
                              void* d_out, int out_size)
{
    const float* x        = (const float*)d_in[0];
    const float* h0_gen   = (const float*)d_in[1];
    const float* c0_gen   = (const float*)d_in[2];
    const float* W_ih_opp = (const float*)d_in[3];
    // d_in[4] = W_hh_opp — unused (zero initial state)
    const float* b_ih_opp = (const float*)d_in[5];
    const float* b_hh_opp = (const float*)d_in[6];
    const float* W_ih_gen = (const float*)d_in[7];
    const float* W_hh_gen = (const float*)d_in[8];
    const float* b_ih_gen = (const float*)d_in[9];
    const float* b_hh_gen = (const float*)d_in[10];
    const float* W1       = (const float*)d_in[11];
    const float* b1       = (const float*)d_in[12];
    const float* W2       = (const float*)d_in[13];
    const float* b2       = (const float*)d_in[14];
    float* out = (float*)d_out;

    net_kernel<<<1, 416>>>(x, h0_gen, c0_gen, W_ih_opp, b_ih_opp, b_hh_opp,
                           W_ih_gen, W_hh_gen, b_ih_gen, b_hh_gen,
                           W1, b1, W2, b2, out);
}